// round 1
// baseline (speedup 1.0000x reference)
#include <cuda_runtime.h>
#include <cstdint>
#include <cstddef>

#define DH __host__ __device__

// ---------------- compile-time DCT constants ----------------
// cos((2p+1)*f*pi/64) with exact integer angle reduction, Taylor on [0, pi/2].
DH constexpr double tcos_core(double x) {
    double x2 = x * x, t = 1.0, s = 1.0;
    for (int i = 1; i <= 12; i++) { t *= -x2 / (double)((2 * i - 1) * (2 * i)); s += t; }
    return s;
}
DH constexpr double dctcosd(int f, int p) {
    int m = ((2 * p + 1) * f) % 128;
    double sg = 1.0;
    if (m > 64) m = 128 - m;
    if (m > 32) { sg = -1.0; m = 64 - m; }
    const double PI = 3.14159265358979323846264338327950288;
    return sg * tcos_core((double)m * PI / 64.0);
}
DH constexpr double rsqrt2c() {
    double g = 0.7;
    for (int i = 0; i < 50; i++) g = 0.5 * (g + 0.5 / g);  // -> sqrt(0.5)
    return g;
}
DH constexpr float c1val(int v, int y) {  // vertical pass: fold c_v
    return (float)(dctcosd(v, y) * (v == 0 ? rsqrt2c() : 1.0));
}
DH constexpr float c2val(int u, int x) {  // horizontal pass: fold c_u and 2/32
    return (float)(dctcosd(u, x) * (u == 0 ? rsqrt2c() : 1.0) * (2.0 / 32.0));
}

// ---------------- template-unrolled stage 1 (vertical DCT, 3 channels) ----------------
template <int Y, int V> struct S1V {
    static __device__ __forceinline__ void run(float py, float pcb, float pcr, float (&a)[3][32]) {
        constexpr float c = c1val(V, Y);
        a[0][V] = fmaf(py,  c, a[0][V]);
        a[1][V] = fmaf(pcb, c, a[1][V]);
        a[2][V] = fmaf(pcr, c, a[2][V]);
        S1V<Y, V + 1>::run(py, pcb, pcr, a);
    }
};
template <int Y> struct S1V<Y, 32> {
    static __device__ __forceinline__ void run(float, float, float, float (&)[3][32]) {}
};

template <int Y> struct S1Y {
    static __device__ __forceinline__ void run(const float* __restrict__ r,
                                               const float* __restrict__ g,
                                               const float* __restrict__ b,
                                               float (&a)[3][32]) {
        float rv = r[Y * 512], gv = g[Y * 512], bv = b[Y * 512];
        float y0  = fmaf(0.299f, rv, fmaf(0.587f, gv, 0.114f * bv));
        float py  = fmaf(2.0f, y0, -1.0f);
        float pcb = (bv - y0) * 1.128f;   // 2*0.564
        float pcr = (rv - y0) * 1.426f;   // 2*0.713
        S1V<Y, 0>::run(py, pcb, pcr, a);
        S1Y<Y + 1>::run(r, g, b, a);
    }
};
template <> struct S1Y<32> {
    static __device__ __forceinline__ void run(const float*, const float*, const float*, float (&)[3][32]) {}
};

// ---------------- template-unrolled stage 2 (horizontal DCT) ----------------
template <int X, int U> struct S2U {
    static __device__ __forceinline__ void run(float p, float (&a)[32]) {
        constexpr float c = c2val(U, X);
        a[U] = fmaf(p, c, a[U]);
        S2U<X, U + 1>::run(p, a);
    }
};
template <int X> struct S2U<X, 32> {
    static __device__ __forceinline__ void run(float, float (&)[32]) {}
};
template <int X> struct S2X {
    static __device__ __forceinline__ void run(const float* __restrict__ t, float (&a)[32]) {
        float p = t[X];
        S2U<X, 0>::run(p, a);
        S2X<X + 1>::run(t, a);
    }
};
template <> struct S2X<32> {
    static __device__ __forceinline__ void run(const float* __restrict__, float (&)[32]) {}
};

// ---------------- permutation derivation from the kernels input ----------------
__device__ int g_pos[1024];  // pos[v*32+u] = output channel index k

__device__ __forceinline__ unsigned long long lanemax_ull(unsigned long long k) {
    #pragma unroll
    for (int o = 16; o; o >>= 1) {
        unsigned long long other = __shfl_xor_sync(0xffffffffu, k, o);
        if (other > k) k = other;
    }
    return k;
}

// One CTA (32 threads) per kernel k. Row y=0 of kernels[k] identifies u via
// orthogonality of the DCT cosine rows; column x=0 identifies v.
__global__ void perm_kernel(const float* __restrict__ ker) {
    int k = blockIdx.x;
    int f = threadIdx.x;  // candidate frequency
    const float* K = ker + (size_t)k * 1024;
    float s = 0.f, t = 0.f;
    #pragma unroll
    for (int x = 0; x < 32; x++) {
        float c = cospif((float)((2 * x + 1) * f) * (1.0f / 64.0f));
        s = fmaf(K[x],      c, s);  // row 0 -> u-score
        t = fmaf(K[x * 32], c, t);  // col 0 -> v-score
    }
    unsigned long long ks = (((unsigned long long)__float_as_uint(fabsf(s))) << 32) | (unsigned)f;
    unsigned long long kt = (((unsigned long long)__float_as_uint(fabsf(t))) << 32) | (unsigned)f;
    ks = lanemax_ull(ks);
    kt = lanemax_ull(kt);
    if (f == 0) {
        int ub = (int)(ks & 31u);
        int vb = (int)(kt & 31u);
        g_pos[vb * 32 + ub] = k;
    }
}

// ---------------- main fused kernel ----------------
// Grid: (ng=2, m=16, b=32). CTA = 256 threads handles one 32-row x 256-col strip
// (8 DCT blocks x 3 channels).
// SMEM tmp layout: tmp[c][v][x] at (c*32+v)*264 + (x/32)*33 + (x%32)
// (group padding makes both STS and the stage-2 LDS conflict-free).
static constexpr int TMP_FLOATS = 3 * 32 * 264;  // 25344 floats = 101376 B

__global__ void __launch_bounds__(256, 2)
dct_main(const float* __restrict__ rgb, float* __restrict__ out) {
    extern __shared__ float tmp[];
    __shared__ int pos_s[1024];

    const int tid = threadIdx.x;
    const int ng = blockIdx.x;   // n-group (8 blocks each)
    const int m  = blockIdx.y;   // block row
    const int b  = blockIdx.z;   // batch

    #pragma unroll
    for (int i = 0; i < 4; i++) pos_s[i * 256 + tid] = g_pos[i * 256 + tid];

    // ---- stage 1: vertical DCT of this thread's pixel column (all 3 channels) ----
    const size_t plane = (size_t)512 * 512;
    const float* base = rgb + (size_t)b * 3 * plane + (size_t)(m * 32) * 512 + ng * 256 + tid;

    float acc[3][32];
    #pragma unroll
    for (int c = 0; c < 3; c++)
        #pragma unroll
        for (int v = 0; v < 32; v++) acc[c][v] = 0.f;

    S1Y<0>::run(base, base + plane, base + 2 * plane, acc);

    const int go = (tid >> 5) * 33 + (tid & 31);
    #pragma unroll
    for (int c = 0; c < 3; c++)
        #pragma unroll
        for (int v = 0; v < 32; v++)
            tmp[(c * 32 + v) * 264 + go] = acc[c][v];

    __syncthreads();

    // ---- stage 2: horizontal DCT. Thread = (v = tid/8, nblk = tid%8). ----
    // Warp = 4 v's x 8 nblk -> each STG.32 covers 4 full 32B sectors.
    const int v = tid >> 3, nblk = tid & 7;
    const int n = ng * 8 + nblk;
    float* ob = out + (((size_t)b * 3072) * 16 + m) * 16 + n;
    const int* pv = pos_s + v * 32;

    #pragma unroll 1
    for (int c = 0; c < 3; c++) {
        float a2[32];
        #pragma unroll
        for (int u = 0; u < 32; u++) a2[u] = 0.f;

        S2X<0>::run(tmp + (c * 32 + v) * 264 + nblk * 33, a2);

        float* obc = ob + (size_t)c * 1024 * 256;
        #pragma unroll
        for (int u = 0; u < 32; u++) {
            obc[(size_t)pv[u] * 256] = a2[u];  // bijective: every output written once
        }
    }
}

// ---------------- launch ----------------
extern "C" void kernel_launch(void* const* d_in, const int* in_sizes, int n_in,
                              void* d_out, int out_size) {
    const float* rgb = (const float*)d_in[0];
    const float* ker = (const float*)d_in[1];
    float* out = (float*)d_out;

    perm_kernel<<<1024, 32>>>(ker);

    cudaFuncSetAttribute(dct_main, cudaFuncAttributeMaxDynamicSharedMemorySize,
                         TMP_FLOATS * (int)sizeof(float));
    dct_main<<<dim3(2, 16, 32), 256, TMP_FLOATS * (int)sizeof(float)>>>(rgb, out);
}

// round 2
// speedup vs baseline: 1.4059x; 1.4059x over previous
#include <cuda_runtime.h>
#include <cstdint>
#include <cstddef>

#define DH __host__ __device__

// ---------------- compile-time DCT constants ----------------
// cos((2p+1)*f*pi/64) with exact integer angle reduction, Taylor on [0, pi/2].
DH constexpr double tcos_core(double x) {
    double x2 = x * x, t = 1.0, s = 1.0;
    for (int i = 1; i <= 12; i++) { t *= -x2 / (double)((2 * i - 1) * (2 * i)); s += t; }
    return s;
}
DH constexpr double dctcosd(int f, int p) {
    int m = ((2 * p + 1) * f) % 128;
    double sg = 1.0;
    if (m > 64) m = 128 - m;
    if (m > 32) { sg = -1.0; m = 64 - m; }
    const double PI = 3.14159265358979323846264338327950288;
    return sg * tcos_core((double)m * PI / 64.0);
}
DH constexpr double rsqrt2c() {
    double g = 0.7;
    for (int i = 0; i < 50; i++) g = 0.5 * (g + 0.5 / g);  // -> sqrt(0.5)
    return g;
}
DH constexpr float c1val(int v, int y) {  // vertical pass: fold c_v
    return (float)(dctcosd(v, y) * (v == 0 ? rsqrt2c() : 1.0));
}
DH constexpr float c2val(int u, int x) {  // horizontal pass: fold c_u and 2/32
    return (float)(dctcosd(u, x) * (u == 0 ? rsqrt2c() : 1.0) * (2.0 / 32.0));
}

// ---------------- stage 1: vertical DCT with reflection butterfly ----------------
// For pair P (rows P and 31-P): even v use s = lo+hi, odd v use d = lo-hi,
// because cos((2(31-y)+1)v pi/64) = (-1)^v cos((2y+1)v pi/64).
template <int P, int V> struct S1V {
    static __device__ __forceinline__ void run(float sy, float sb, float sr,
                                               float dy, float db, float dr,
                                               float (&a)[3][32]) {
        constexpr float ce = c1val(2 * V,     P);
        constexpr float co = c1val(2 * V + 1, P);
        a[0][2 * V]     = fmaf(sy, ce, a[0][2 * V]);
        a[1][2 * V]     = fmaf(sb, ce, a[1][2 * V]);
        a[2][2 * V]     = fmaf(sr, ce, a[2][2 * V]);
        a[0][2 * V + 1] = fmaf(dy, co, a[0][2 * V + 1]);
        a[1][2 * V + 1] = fmaf(db, co, a[1][2 * V + 1]);
        a[2][2 * V + 1] = fmaf(dr, co, a[2][2 * V + 1]);
        S1V<P, V + 1>::run(sy, sb, sr, dy, db, dr, a);
    }
};
template <int P> struct S1V<P, 16> {
    static __device__ __forceinline__ void run(float, float, float, float, float, float,
                                               float (&)[3][32]) {}
};

__device__ __forceinline__ void ycbcr(float rv, float gv, float bv,
                                      float& py, float& pcb, float& pcr) {
    float y0 = fmaf(0.299f, rv, fmaf(0.587f, gv, 0.114f * bv));
    py  = fmaf(2.0f, y0, -1.0f);
    pcb = (bv - y0) * 1.128f;   // 2*0.564
    pcr = (rv - y0) * 1.426f;   // 2*0.713
}

template <int P> struct S1P {
    static __device__ __forceinline__ void run(const float* __restrict__ r,
                                               const float* __restrict__ g,
                                               const float* __restrict__ b,
                                               float (&a)[3][32]) {
        constexpr int Q = 31 - P;
        float rl = r[P * 512], gl = g[P * 512], bl = b[P * 512];
        float rh = r[Q * 512], gh = g[Q * 512], bh = b[Q * 512];
        float pyl, pcbl, pcrl, pyh, pcbh, pcrh;
        ycbcr(rl, gl, bl, pyl, pcbl, pcrl);
        ycbcr(rh, gh, bh, pyh, pcbh, pcrh);
        float sy = pyl + pyh,  dy = pyl - pyh;
        float sb = pcbl + pcbh, db = pcbl - pcbh;
        float sr = pcrl + pcrh, dr = pcrl - pcrh;
        S1V<P, 0>::run(sy, sb, sr, dy, db, dr, a);
        S1P<P + 1>::run(r, g, b, a);
    }
};
template <> struct S1P<16> {
    static __device__ __forceinline__ void run(const float*, const float*, const float*,
                                               float (&)[3][32]) {}
};

// ---------------- stage 2: horizontal DCT with reflection butterfly ----------------
template <int P, int U> struct S2U {
    static __device__ __forceinline__ void run(float s, float d, float (&a)[32]) {
        constexpr float ce = c2val(2 * U,     P);
        constexpr float co = c2val(2 * U + 1, P);
        a[2 * U]     = fmaf(s, ce, a[2 * U]);
        a[2 * U + 1] = fmaf(d, co, a[2 * U + 1]);
        S2U<P, U + 1>::run(s, d, a);
    }
};
template <int P> struct S2U<P, 16> {
    static __device__ __forceinline__ void run(float, float, float (&)[32]) {}
};
template <int P> struct S2P {
    static __device__ __forceinline__ void run(const float* __restrict__ t, float (&a)[32]) {
        float lo = t[P], hi = t[31 - P];
        S2U<P, 0>::run(lo + hi, lo - hi, a);
        S2P<P + 1>::run(t, a);
    }
};
template <> struct S2P<16> {
    static __device__ __forceinline__ void run(const float* __restrict__, float (&)[32]) {}
};

// ---------------- permutation derivation from the kernels input ----------------
__device__ int g_pos[1024];  // pos[v*32+u] = output channel index k

__device__ __forceinline__ unsigned long long lanemax_ull(unsigned long long k) {
    #pragma unroll
    for (int o = 16; o; o >>= 1) {
        unsigned long long other = __shfl_xor_sync(0xffffffffu, k, o);
        if (other > k) k = other;
    }
    return k;
}

// One warp per kernel k (8 warps/CTA, 128 CTAs). Row y=0 of kernels[k]
// identifies u via orthogonality of the DCT cosine rows; column x=0 identifies v.
__global__ void perm_kernel(const float* __restrict__ ker) {
    int k = blockIdx.x * 8 + (threadIdx.x >> 5);
    int f = threadIdx.x & 31;  // candidate frequency
    const float* K = ker + (size_t)k * 1024;
    float s = 0.f, t = 0.f;
    #pragma unroll
    for (int x = 0; x < 32; x++) {
        float c = cospif((float)((2 * x + 1) * f) * (1.0f / 64.0f));
        s = fmaf(K[x],      c, s);  // row 0 -> u-score
        t = fmaf(K[x * 32], c, t);  // col 0 -> v-score
    }
    unsigned long long ks = (((unsigned long long)__float_as_uint(fabsf(s))) << 32) | (unsigned)f;
    unsigned long long kt = (((unsigned long long)__float_as_uint(fabsf(t))) << 32) | (unsigned)f;
    ks = lanemax_ull(ks);
    kt = lanemax_ull(kt);
    if (f == 0) {
        int ub = (int)(ks & 31u);
        int vb = (int)(kt & 31u);
        g_pos[vb * 32 + ub] = k;
    }
}

// ---------------- main fused kernel ----------------
// Grid: (ng=2, m=16, b=32). CTA = 256 threads handles one 32-row x 256-col strip
// (8 DCT blocks x 3 channels).
// SMEM tmp layout: tmp[c][v][x] at (c*32+v)*264 + (x/32)*33 + (x%32)
// (group padding makes both STS and the stage-2 LDS conflict-free).
static constexpr int TMP_FLOATS = 3 * 32 * 264;  // 25344 floats = 101376 B

__global__ void __launch_bounds__(256, 2)
dct_main(const float* __restrict__ rgb, float* __restrict__ out) {
    extern __shared__ float tmp[];
    __shared__ int pos_s[1024];

    const int tid = threadIdx.x;
    const int ng = blockIdx.x;   // n-group (8 blocks each)
    const int m  = blockIdx.y;   // block row
    const int b  = blockIdx.z;   // batch

    #pragma unroll
    for (int i = 0; i < 4; i++) pos_s[i * 256 + tid] = g_pos[i * 256 + tid];

    // ---- stage 1: vertical butterfly DCT of this thread's pixel column ----
    const size_t plane = (size_t)512 * 512;
    const float* base = rgb + (size_t)b * 3 * plane + (size_t)(m * 32) * 512 + ng * 256 + tid;

    float acc[3][32];
    #pragma unroll
    for (int c = 0; c < 3; c++)
        #pragma unroll
        for (int v = 0; v < 32; v++) acc[c][v] = 0.f;

    S1P<0>::run(base, base + plane, base + 2 * plane, acc);

    const int go = (tid >> 5) * 33 + (tid & 31);
    #pragma unroll
    for (int c = 0; c < 3; c++)
        #pragma unroll
        for (int v = 0; v < 32; v++)
            tmp[(c * 32 + v) * 264 + go] = acc[c][v];

    __syncthreads();

    // ---- stage 2: horizontal butterfly DCT. Thread = (v = tid/8, nblk = tid%8). ----
    // Warp = 4 v's x 8 nblk -> each STG.32 covers 4 full 32B sectors.
    const int v = tid >> 3, nblk = tid & 7;
    const int n = ng * 8 + nblk;
    float* ob = out + (((size_t)b * 3072) * 16 + m) * 16 + n;
    const int* pv = pos_s + v * 32;

    #pragma unroll 1
    for (int c = 0; c < 3; c++) {
        float a2[32];
        #pragma unroll
        for (int u = 0; u < 32; u++) a2[u] = 0.f;

        S2P<0>::run(tmp + (c * 32 + v) * 264 + nblk * 33, a2);

        float* obc = ob + (size_t)c * 1024 * 256;
        #pragma unroll
        for (int u = 0; u < 32; u++) {
            obc[(size_t)pv[u] * 256] = a2[u];  // bijective: every output written once
        }
    }
}

// ---------------- launch ----------------
extern "C" void kernel_launch(void* const* d_in, const int* in_sizes, int n_in,
                              void* d_out, int out_size) {
    const float* rgb = (const float*)d_in[0];
    const float* ker = (const float*)d_in[1];
    float* out = (float*)d_out;

    perm_kernel<<<128, 256>>>(ker);

    cudaFuncSetAttribute(dct_main, cudaFuncAttributeMaxDynamicSharedMemorySize,
                         TMP_FLOATS * (int)sizeof(float));
    dct_main<<<dim3(2, 16, 32), 256, TMP_FLOATS * (int)sizeof(float)>>>(rgb, out);
}